// round 13
// baseline (speedup 1.0000x reference)
#include <cuda_runtime.h>
#include <cuda_fp16.h>
#include <cstdint>

#define S    1024
#define D    1024
#define PP   2816
#define R    64
#define E    8
#define MM   16
#define SPAD 1152
#define NT   (SPAD/16)   // 72 sixteen-row tiles

// ---------------- device scratch (static, no runtime alloc) ----------------
__device__ float g_alpha[2][E][MM];          // softmax mixture weights (0=up,1=gate)
__device__ float g_up_mixed[E*D*R];          // [E][D][R]
__device__ float g_gate_mixed[E*D*R];
__device__ float g_aut[E*R*PP];              // transposed up adapters [E][R][P]
__device__ float g_agt[E*R*PP];              // transposed gate adapters
__device__ int   g_perm[SPAD];               // permuted row -> token (or -1 pad)
__device__ float g_wrow[SPAD];               // routing weight per permuted row
__device__ int   g_poff[E+1];                // padded expert offsets (mult of 16)
__device__ int   g_etile[NT];                // expert per 16-row tile (or -1)
__device__ float g_tpart[4*SPAD*2*R + 64*128]; // split-K partials (+pad for 32-row windows)
__device__ __half g_inter[SPAD*PP];          // silu(gate)*up, fp16

__device__ __forceinline__ uint32_t s2u(const void* p) {
    uint32_t a;
    asm("{ .reg .u64 t; cvta.to.shared.u64 t, %1; cvt.u32.u64 %0, t; }" : "=r"(a) : "l"(p));
    return a;
}

// ---------------- K1: routing, permutation, alphas ----------------
__global__ __launch_bounds__(1024) void k_route(const int* __restrict__ eidx,
                                                const float* __restrict__ ew,
                                                const float* __restrict__ ulog,
                                                const float* __restrict__ glog) {
    __shared__ int wcnt[32][E];
    __shared__ int woff[32][E];
    __shared__ int poff_s[E+1];
    int t = threadIdx.x;
    int e = eidx[t];                      // K = 1
    int w = t >> 5, lane = t & 31;
    if (lane < E) wcnt[w][lane] = 0;
    __syncthreads();
    unsigned mask = __match_any_sync(0xffffffffu, e);
    int posw = __popc(mask & ((1u << lane) - 1u));
    if (posw == 0) wcnt[w][e] = __popc(mask);
    __syncthreads();
    if (t < 256) {                        // exclusive prefix over warps per expert
        int e2 = t >> 5, w2 = t & 31;
        int sacc = 0;
        for (int ww = 0; ww < w2; ww++) sacc += wcnt[ww][e2];
        woff[w2][e2] = sacc;
    }
    __syncthreads();
    if (t == 0) {
        int o = 0;
        for (int e2 = 0; e2 < E; e2++) {
            poff_s[e2] = o;
            int c = woff[31][e2] + wcnt[31][e2];
            o += (c + 15) & ~15;          // pad each expert to 16 rows
        }
        poff_s[E] = o;
        for (int i = 0; i <= E; i++) g_poff[i] = poff_s[i];
    }
    __syncthreads();
    for (int i = t; i < SPAD; i += 1024) { g_perm[i] = -1; g_wrow[i] = 0.f; }
    __syncthreads();
    int row = poff_s[e] + woff[w][e] + posw;
    g_perm[row] = t;
    g_wrow[row] = ew[t];
    if (t < NT) {
        int r0 = t * 16; int ee = -1;
        for (int e2 = 0; e2 < E; e2++)
            if (r0 >= poff_s[e2] && r0 < poff_s[e2+1]) ee = e2;
        g_etile[t] = ee;
    }
    if (t < 2 * E) {                      // softmax over M=16
        int which = t & 1, e2 = t >> 1;
        const float* L = (which ? glog : ulog) + e2 * MM;
        float mx = L[0];
        for (int m = 1; m < MM; m++) mx = fmaxf(mx, L[m]);
        float sum = 0.f, ex[MM];
        for (int m = 0; m < MM; m++) { ex[m] = __expf(L[m] - mx); sum += ex[m]; }
        float inv = 1.f / sum;
        for (int m = 0; m < MM; m++) g_alpha[which][e2][m] = ex[m] * inv;
    }
}

// ---------------- K2: mixed bases [E,D,R] = alpha @ bank ----------------
__global__ __launch_bounds__(256) void k_mixed(const float* __restrict__ ubank,
                                               const float* __restrict__ gbank) {
    __shared__ float al[2 * E * MM];      // 256 floats
    int t = threadIdx.x;
    al[t] = ((const float*)g_alpha)[t];
    __syncthreads();
    int r = t & 63, dl = t >> 6;
    int d = blockIdx.x * 4 + dl;
    float au[E], ag[E];
    #pragma unroll
    for (int e = 0; e < E; e++) { au[e] = 0.f; ag[e] = 0.f; }
    #pragma unroll
    for (int m = 0; m < MM; m++) {
        float bu = ubank[(m * D + d) * R + r];
        float bg = gbank[(m * D + d) * R + r];
        #pragma unroll
        for (int e = 0; e < E; e++) {
            au[e] += al[e * MM + m] * bu;
            ag[e] += al[E * MM + e * MM + m] * bg;
        }
    }
    #pragma unroll
    for (int e = 0; e < E; e++) {
        g_up_mixed  [(e * D + d) * R + r] = au[e];
        g_gate_mixed[(e * D + d) * R + r] = ag[e];
    }
}

// ---------------- K2b: transpose adapters [E,P,R] -> [E,R,P] ----------------
__global__ __launch_bounds__(256) void k_trans(const float* __restrict__ uA,
                                               const float* __restrict__ gA) {
    int e = blockIdx.z >> 1, which = blockIdx.z & 1;
    const float* src = which ? gA : uA;
    float* dst = which ? g_agt : g_aut;
    int p0 = blockIdx.x * 32, r0 = blockIdx.y * 32;
    __shared__ float sm[32][33];
    int tx = threadIdx.x, ty = threadIdx.y;
    for (int i = ty; i < 32; i += 8)
        sm[i][tx] = src[(e * PP + p0 + i) * R + r0 + tx];
    __syncthreads();
    for (int i = ty; i < 32; i += 8)
        dst[(e * R + r0 + i) * PP + p0 + tx] = sm[tx][i];
}

// ---------------- K3: t = X_gathered @ mixed (split-K=4, pipelined smem) ----------------
#define TCK 32
__global__ __launch_bounds__(256) void k_tproj(const float* __restrict__ x) {
    int tile = blockIdx.x;
    int e = g_etile[tile];
    if (e < 0) return;
    int split = blockIdx.y, d0 = split * 256;
    int base = tile * 16;
    __shared__ float xs[16][256];         // X tile, d-contiguous per row
    __shared__ float ms[3][TCK][128];     // mixed chunks: [d][col] col<64 up, >=64 gate
    __shared__ int ps[16];
    int t = threadIdx.x;
    if (t < 16) ps[t] = g_perm[base + t];
    __syncthreads();

    // X tile via cp.async (one group): 16 rows x 64 f4
    #pragma unroll
    for (int i = 0; i < 4; i++) {
        int q = t + i * 256;
        int row = q >> 6, c4 = q & 63;
        int s = ps[row];
        unsigned sa = (unsigned)__cvta_generic_to_shared(&xs[row][c4 * 4]);
        const float* src = &x[(size_t)(s < 0 ? 0 : s) * D + d0 + c4 * 4];
        int sz = (s >= 0) ? 16 : 0;
        asm volatile("cp.async.cg.shared.global [%0], [%1], 16, %2;"
                     :: "r"(sa), "l"(src), "r"(sz));
    }
    asm volatile("cp.async.commit_group;");

    const float* upb = g_up_mixed   + (size_t)(e * D + d0) * R;
    const float* gtb = g_gate_mixed + (size_t)(e * D + d0) * R;
    auto load_ms = [&](int ck, int buf) {
        #pragma unroll
        for (int i = 0; i < 4; i++) {
            int q = t + i * 256;          // 1024 f4 slots = 32 d x 32 f4
            int d = q >> 5, c = q & 31;   // c<16: up r-slot, c>=16: gate r-slot
            const float* src = (c < 16)
                ? upb + (size_t)(ck * TCK + d) * R + c * 4
                : gtb + (size_t)(ck * TCK + d) * R + (c - 16) * 4;
            unsigned sa = (unsigned)__cvta_generic_to_shared(&ms[buf][d][c * 4]);
            asm volatile("cp.async.cg.shared.global [%0], [%1], 16, 16;"
                         :: "r"(sa), "l"(src));
        }
        asm volatile("cp.async.commit_group;");
    };

    load_ms(0, 0);
    load_ms(1, 1);

    int col = t & 127, rg = t >> 7;       // col: 0-63 up, 64-127 gate; rg: row group
    float acc[8] = {};
    const int NCK = 256 / TCK;            // 8 chunks

    for (int ck = 0; ck < NCK; ck++) {
        if (ck + 2 < NCK) { asm volatile("cp.async.wait_group 1;"); }
        else              { asm volatile("cp.async.wait_group 0;"); }
        __syncthreads();
        if (ck + 2 < NCK) load_ms(ck + 2, (ck + 2) % 3);
        const float (*mb)[128] = ms[ck % 3];
        #pragma unroll
        for (int dd = 0; dd < TCK; dd += 4) {
            float4 xv[8];
            #pragma unroll
            for (int i = 0; i < 8; i++)
                xv[i] = *(const float4*)&xs[rg * 8 + i][ck * TCK + dd];
            #pragma unroll
            for (int j = 0; j < 4; j++) {
                float m = mb[dd + j][col];
                #pragma unroll
                for (int i = 0; i < 8; i++)
                    acc[i] += ((const float*)&xv[i])[j] * m;
            }
        }
        __syncthreads();
    }
    #pragma unroll
    for (int i = 0; i < 8; i++)
        g_tpart[(size_t)(split * SPAD + base + rg * 8 + i) * 128 + col] = acc[i];
}

// ---------------- K4: expert-persistent adapters + silu -> fp16 inter ----------
// grid (22, E, 2): z splits the expert's 32-row windows for SM load balance.
// dyn smem: au[64][128] | ag[64][128] | ts[32][128] = 81920 B
__global__ __launch_bounds__(256) void k_adapt() {
    extern __shared__ float sm4[];
    float* sau = sm4;                     // [64][128]
    float* sag = sm4 + 64 * 128;          // [64][128]
    float* ts  = sm4 + 2 * 64 * 128;      // [32][128]
    int e = blockIdx.y;
    int p0 = blockIdx.x * 128;
    int t = threadIdx.x;
    int r0 = g_poff[e], r1 = g_poff[e + 1];
    int nw = (r1 - r0 + 31) >> 5;
    int hh = blockIdx.z;
    int w0 = (nw * hh) >> 1, w1 = (nw * (hh + 1)) >> 1;
    if (w0 >= w1) return;

    const float* aup = g_aut + (size_t)e * R * PP + p0;
    const float* agp = g_agt + (size_t)e * R * PP + p0;
    #pragma unroll
    for (int i = 0; i < 8; i++) {
        int q = t + i * 256;              // over 2048 f4
        int r = q >> 5, c4 = q & 31;
        unsigned sa = (unsigned)__cvta_generic_to_shared(&sau[r * 128 + c4 * 4]);
        asm volatile("cp.async.cg.shared.global [%0], [%1], 16, 16;"
                     :: "r"(sa), "l"(aup + (size_t)r * PP + c4 * 4));
        unsigned sg = (unsigned)__cvta_generic_to_shared(&sag[r * 128 + c4 * 4]);
        asm volatile("cp.async.cg.shared.global [%0], [%1], 16, 16;"
                     :: "r"(sg), "l"(agp + (size_t)r * PP + c4 * 4));
    }
    asm volatile("cp.async.commit_group;");
    asm volatile("cp.async.wait_group 0;");
    __syncthreads();

    int c = t & 31, rg = t >> 5;          // c: 4 cols each; rg: warp -> 4 rows
    for (int wI = w0; wI < w1; wI++) {
        int base = r0 + wI * 32;
        __syncthreads();                  // ts write-after-read fence
        // reduce 4 split-K partials into ts (1024 f4 / 256 thr = 4 each)
        #pragma unroll
        for (int i = 0; i < 4; i++) {
            int q = t + i * 256;
            int row = q >> 5, c4 = q & 31;
            float4 acc = make_float4(0.f, 0.f, 0.f, 0.f);
            #pragma unroll
            for (int sp = 0; sp < 4; sp++) {
                float4 v = *(const float4*)&g_tpart[(size_t)(sp * SPAD + base + row) * 128 + c4 * 4];
                acc.x += v.x; acc.y += v.y; acc.z += v.z; acc.w += v.w;
            }
            *(float4*)&ts[row * 128 + c4 * 4] = acc;
        }
        __syncthreads();

        float accu[4][4] = {}, accg[4][4] = {};
        #pragma unroll 4
        for (int r = 0; r < R; r++) {
            float4 au  = *(const float4*)&sau[r * 128 + c * 4];
            float4 ag4 = *(const float4*)&sag[r * 128 + c * 4];
            #pragma unroll
            for (int i = 0; i < 4; i++) {
                float tu  = ts[(rg * 4 + i) * 128 + r];
                float tg2 = ts[(rg * 4 + i) * 128 + 64 + r];
                accu[i][0] += tu * au.x;  accu[i][1] += tu * au.y;
                accu[i][2] += tu * au.z;  accu[i][3] += tu * au.w;
                accg[i][0] += tg2 * ag4.x; accg[i][1] += tg2 * ag4.y;
                accg[i][2] += tg2 * ag4.z; accg[i][3] += tg2 * ag4.w;
            }
        }
        #pragma unroll
        for (int i = 0; i < 4; i++) {
            int row = base + rg * 4 + i;
            if (row < r1) {
                float sv[4];
                #pragma unroll
                for (int cc = 0; cc < 4; cc++) {
                    float gv = accg[i][cc], uv = accu[i][cc];
                    sv[cc] = uv * gv / (1.f + __expf(-gv));   // up * silu(gate)
                }
                __half2 h0 = __floats2half2_rn(sv[0], sv[1]);
                __half2 h1 = __floats2half2_rn(sv[2], sv[3]);
                uint2 u;
                u.x = *(unsigned*)&h0; u.y = *(unsigned*)&h1;
                *(uint2*)&g_inter[(size_t)row * PP + p0 + c * 4] = u;
            }
        }
    }
}

// ---------------- K5: routed down GEMM, fp16 mma m16n8k16, 4-stage ring ----------
// Block 256m x 64n, 512 thr (16 warps of 32m x 32n). Warps whose 32-row slice is
// entirely padding skip fragment loads + mma (their output is masked anyway).
// dyn smem: Ash 4x12288 | Bsh 4x3072 | Braw 4x4096 = 77824 B
#define AS4   (256*48)      // A stage bytes (256 rows x 48B, 16 halfs data + pad)
#define BS4   (64*48)       // B stage bytes
#define BRAWF (64*16)       // B raw floats per stage
__global__ __launch_bounds__(512) void k_down(const float* __restrict__ down,
                                              float* __restrict__ out) {
    extern __shared__ char sm5[];
    char* AshP = sm5;
    char* BshP = sm5 + 4 * AS4;
    float* Braw = (float*)(sm5 + 4 * AS4 + 4 * BS4);
    uint32_t sA = s2u(sm5);
    uint32_t sB = sA + 4 * AS4;
    uint32_t sR = sB + 4 * BS4;
    int e = blockIdx.y;
    int r0 = g_poff[e], r1 = g_poff[e + 1];
    int d0 = blockIdx.x * 64;
    const float* Bg = down + ((size_t)e * D + d0) * PP;
    int t = threadIdx.x, lane = t & 31, gq = lane >> 2, tq = lane & 3;
    int w = t >> 5, wm = w & 7, wn = w >> 3;
    const int NKT = PP / 16;              // 176

    for (int rowBase = r0; rowBase < r1; rowBase += 256) {
        int rem = min(256, r1 - rowBase);
        const __half* Ag = g_inter + (size_t)rowBase * PP;
        bool act = (wm * 32 < rem);       // warp has at least one real row

        auto issue = [&](int fs) {
            int buf = fs & 3, kk = fs * 16;
            {   // A: 256 rows x 2 chunks of 8 halfs
                int row = t >> 1, c = t & 1;
                bool ok = row < rem;
                const __half* src = ok ? (Ag + (size_t)row * PP + kk + c * 8) : Ag;
                uint32_t sa = sA + buf * AS4 + row * 48 + c * 16;
                int sz = ok ? 16 : 0;
                asm volatile("cp.async.cg.shared.global [%0], [%1], 16, %2;"
                             :: "r"(sa), "l"(src), "r"(sz));
            }
            if (t < 256) {  // B raw fp32: 64 rows x 4 chunks of 4 floats
                int row = t >> 2, c = t & 3;
                const float* src = Bg + (size_t)row * PP + kk + c * 4;
                uint32_t sa = sR + buf * (BRAWF * 4) + (row * 16 + c * 4) * 4;
                asm volatile("cp.async.cg.shared.global [%0], [%1], 16, 16;"
                             :: "r"(sa), "l"(src));
            }
            asm volatile("cp.async.commit_group;" ::: "memory");
        };
        auto convertB = [&](int cs) {
            int buf = cs & 3;
            if (t < 256) {
                int n = t >> 2, jf = t & 3;
                float4 v = *(const float4*)&Braw[buf * BRAWF + n * 16 + jf * 4];
                __half2 h0 = __floats2half2_rn(v.x, v.y);
                __half2 h1 = __floats2half2_rn(v.z, v.w);
                uint2 u; u.x = *(unsigned*)&h0; u.y = *(unsigned*)&h1;
                *(uint2*)(BshP + buf * BS4 + n * 48 + jf * 8) = u;
            }
        };

        issue(0); issue(1); issue(2);
        asm volatile("cp.async.wait_group 2;" ::: "memory");
        __syncthreads();
        convertB(0);

        float acc[2][4][4] = {};
        for (int kt = 0; kt < NKT; kt++) {
            if (kt + 1 < NKT) { asm volatile("cp.async.wait_group 1;" ::: "memory"); }
            else              { asm volatile("cp.async.wait_group 0;" ::: "memory"); }
            __syncthreads();
            if (kt + 3 < NKT) issue(kt + 3);
            if (kt + 1 < NKT) convertB(kt + 1);
            if (act) {
                const char* Ab = AshP + (kt & 3) * AS4;
                const char* Bb = BshP + (kt & 3) * BS4;
                unsigned a[2][4], b[4][2];
                #pragma unroll
                for (int mf = 0; mf < 2; mf++) {
                    int mr = wm * 32 + mf * 16 + gq;
                    a[mf][0] = *(const unsigned*)(Ab +  mr      * 48 + tq * 4);
                    a[mf][1] = *(const unsigned*)(Ab + (mr + 8) * 48 + tq * 4);
                    a[mf][2] = *(const unsigned*)(Ab +  mr      * 48 + 16 + tq * 4);
                    a[mf][3] = *(const unsigned*)(Ab + (mr + 8) * 48 + 16 + tq * 4);
                }
                #pragma unroll
                for (int nf = 0; nf < 4; nf++) {
                    int nr = wn * 32 + nf * 8 + gq;
                    b[nf][0] = *(const unsigned*)(Bb + nr * 48 + tq * 4);
                    b[nf][1] = *(const unsigned*)(Bb + nr * 48 + 16 + tq * 4);
                }
                #pragma unroll
                for (int mf = 0; mf < 2; mf++)
                    #pragma unroll
                    for (int nf = 0; nf < 4; nf++)
                        asm volatile(
                            "mma.sync.aligned.m16n8k16.row.col.f32.f16.f16.f32 "
                            "{%0,%1,%2,%3}, {%4,%5,%6,%7}, {%8,%9}, {%0,%1,%2,%3};"
                            : "+f"(acc[mf][nf][0]), "+f"(acc[mf][nf][1]),
                              "+f"(acc[mf][nf][2]), "+f"(acc[mf][nf][3])
                            : "r"(a[mf][0]), "r"(a[mf][1]), "r"(a[mf][2]), "r"(a[mf][3]),
                              "r"(b[nf][0]), "r"(b[nf][1]));
            }
        }
        // epilogue: scale by routing weight, scatter to original token rows
        if (act) {
            #pragma unroll
            for (int mf = 0; mf < 2; mf++) {
                #pragma unroll
                for (int h = 0; h < 2; h++) {
                    int m = wm * 32 + mf * 16 + gq + h * 8;
                    if (m < rem) {
                        int s = g_perm[rowBase + m];
                        if (s >= 0) {
                            float wv = g_wrow[rowBase + m];
                            #pragma unroll
                            for (int nf = 0; nf < 4; nf++) {
                                int n = d0 + wn * 32 + nf * 8 + tq * 2;
                                float2 v;
                                v.x = acc[mf][nf][h * 2 + 0] * wv;
                                v.y = acc[mf][nf][h * 2 + 1] * wv;
                                *(float2*)&out[(size_t)s * D + n] = v;
                            }
                        }
                    }
                }
            }
        }
        __syncthreads();                  // reuse smem next rowBase iter
    }
}

// ---------------- launch ----------------
extern "C" void kernel_launch(void* const* d_in, const int* in_sizes, int n_in,
                              void* d_out, int out_size) {
    const float* x     = (const float*)d_in[0];
    const int*   eidx  = (const int*)  d_in[1];
    const float* ew    = (const float*)d_in[2];
    const float* uA    = (const float*)d_in[3];
    const float* gA    = (const float*)d_in[4];
    const float* ulog  = (const float*)d_in[5];
    const float* glog  = (const float*)d_in[6];
    const float* down  = (const float*)d_in[7];
    const float* ubank = (const float*)d_in[8];
    const float* gbank = (const float*)d_in[9];
    float* out = (float*)d_out;

    const int ADAPT_SMEM = (2 * 64 * 128 + 32 * 128) * 4;           // 81920
    const int DOWN_SMEM  = 4 * AS4 + 4 * BS4 + 4 * BRAWF * 4;       // 77824
    cudaFuncSetAttribute(k_adapt, cudaFuncAttributeMaxDynamicSharedMemorySize, ADAPT_SMEM);
    cudaFuncSetAttribute(k_down,  cudaFuncAttributeMaxDynamicSharedMemorySize, DOWN_SMEM);

    k_route<<<1, 1024>>>(eidx, ew, ulog, glog);
    k_mixed<<<256, 256>>>(ubank, gbank);
    k_trans<<<dim3(PP / 32, R / 32, 2 * E), dim3(32, 8)>>>(uA, gA);
    k_tproj<<<dim3(NT, 4), 256>>>(x);
    k_adapt<<<dim3(PP / 128, E, 2), 256, ADAPT_SMEM>>>();
    k_down<<<dim3(D / 64, E), 512, DOWN_SMEM>>>(down, out);
}

// round 15
// speedup vs baseline: 1.2474x; 1.2474x over previous
#include <cuda_runtime.h>
#include <cuda_fp16.h>
#include <cstdint>

#define S    1024
#define D    1024
#define PP   2816
#define R    64
#define E    8
#define MM   16
#define SPAD 1152
#define NT   (SPAD/16)   // 72 sixteen-row tiles

// ---------------- device scratch (static, no runtime alloc) ----------------
__device__ float g_alpha[2][E][MM];          // softmax mixture weights (0=up,1=gate)
__device__ float g_up_mixed[E*D*R];          // [E][D][R]
__device__ float g_gate_mixed[E*D*R];
__device__ float g_aut[E*R*PP];              // transposed up adapters [E][R][P]
__device__ float g_agt[E*R*PP];              // transposed gate adapters
__device__ int   g_perm[SPAD];               // permuted row -> token (or -1 pad)
__device__ float g_wrow[SPAD];               // routing weight per permuted row
__device__ int   g_poff[E+1];                // padded expert offsets (mult of 16)
__device__ int   g_etile[NT];                // expert per 16-row tile (or -1)
__device__ float g_tpart[4*SPAD*2*R + 64*128]; // split-K partials (+pad for 32-row windows)
__device__ __half g_inter[SPAD*PP];          // silu(gate)*up, fp16

__device__ __forceinline__ uint32_t s2u(const void* p) {
    uint32_t a;
    asm("{ .reg .u64 t; cvta.to.shared.u64 t, %1; cvt.u32.u64 %0, t; }" : "=r"(a) : "l"(p));
    return a;
}

// ---------------- K1: routing, permutation, alphas ----------------
__global__ __launch_bounds__(1024) void k_route(const int* __restrict__ eidx,
                                                const float* __restrict__ ew,
                                                const float* __restrict__ ulog,
                                                const float* __restrict__ glog) {
    __shared__ int wcnt[32][E];
    __shared__ int woff[32][E];
    __shared__ int poff_s[E+1];
    int t = threadIdx.x;
    int e = eidx[t];                      // K = 1
    int w = t >> 5, lane = t & 31;
    if (lane < E) wcnt[w][lane] = 0;
    __syncthreads();
    unsigned mask = __match_any_sync(0xffffffffu, e);
    int posw = __popc(mask & ((1u << lane) - 1u));
    if (posw == 0) wcnt[w][e] = __popc(mask);
    __syncthreads();
    if (t < 256) {                        // exclusive prefix over warps per expert
        int e2 = t >> 5, w2 = t & 31;
        int sacc = 0;
        for (int ww = 0; ww < w2; ww++) sacc += wcnt[ww][e2];
        woff[w2][e2] = sacc;
    }
    __syncthreads();
    if (t == 0) {
        int o = 0;
        for (int e2 = 0; e2 < E; e2++) {
            poff_s[e2] = o;
            int c = woff[31][e2] + wcnt[31][e2];
            o += (c + 15) & ~15;          // pad each expert to 16 rows
        }
        poff_s[E] = o;
        for (int i = 0; i <= E; i++) g_poff[i] = poff_s[i];
    }
    __syncthreads();
    for (int i = t; i < SPAD; i += 1024) { g_perm[i] = -1; g_wrow[i] = 0.f; }
    __syncthreads();
    int row = poff_s[e] + woff[w][e] + posw;
    g_perm[row] = t;
    g_wrow[row] = ew[t];
    if (t < NT) {
        int r0 = t * 16; int ee = -1;
        for (int e2 = 0; e2 < E; e2++)
            if (r0 >= poff_s[e2] && r0 < poff_s[e2+1]) ee = e2;
        g_etile[t] = ee;
    }
    if (t < 2 * E) {                      // softmax over M=16
        int which = t & 1, e2 = t >> 1;
        const float* L = (which ? glog : ulog) + e2 * MM;
        float mx = L[0];
        for (int m = 1; m < MM; m++) mx = fmaxf(mx, L[m]);
        float sum = 0.f, ex[MM];
        for (int m = 0; m < MM; m++) { ex[m] = __expf(L[m] - mx); sum += ex[m]; }
        float inv = 1.f / sum;
        for (int m = 0; m < MM; m++) g_alpha[which][e2][m] = ex[m] * inv;
    }
}

// ---------------- K2: mixed bases [E,D,R] = alpha @ bank ----------------
__global__ __launch_bounds__(256) void k_mixed(const float* __restrict__ ubank,
                                               const float* __restrict__ gbank) {
    __shared__ float al[2 * E * MM];      // 256 floats
    int t = threadIdx.x;
    al[t] = ((const float*)g_alpha)[t];
    __syncthreads();
    int r = t & 63, dl = t >> 6;
    int d = blockIdx.x * 4 + dl;
    float au[E], ag[E];
    #pragma unroll
    for (int e = 0; e < E; e++) { au[e] = 0.f; ag[e] = 0.f; }
    #pragma unroll
    for (int m = 0; m < MM; m++) {
        float bu = ubank[(m * D + d) * R + r];
        float bg = gbank[(m * D + d) * R + r];
        #pragma unroll
        for (int e = 0; e < E; e++) {
            au[e] += al[e * MM + m] * bu;
            ag[e] += al[E * MM + e * MM + m] * bg;
        }
    }
    #pragma unroll
    for (int e = 0; e < E; e++) {
        g_up_mixed  [(e * D + d) * R + r] = au[e];
        g_gate_mixed[(e * D + d) * R + r] = ag[e];
    }
}

// ---------------- K2b: transpose adapters [E,P,R] -> [E,R,P] ----------------
__global__ __launch_bounds__(256) void k_trans(const float* __restrict__ uA,
                                               const float* __restrict__ gA) {
    int e = blockIdx.z >> 1, which = blockIdx.z & 1;
    const float* src = which ? gA : uA;
    float* dst = which ? g_agt : g_aut;
    int p0 = blockIdx.x * 32, r0 = blockIdx.y * 32;
    __shared__ float sm[32][33];
    int tx = threadIdx.x, ty = threadIdx.y;
    for (int i = ty; i < 32; i += 8)
        sm[i][tx] = src[(e * PP + p0 + i) * R + r0 + tx];
    __syncthreads();
    for (int i = ty; i < 32; i += 8)
        dst[(e * R + r0 + i) * PP + p0 + tx] = sm[tx][i];
}

// ---------------- K3: t = X_gathered @ mixed (split-K=4, pipelined smem) ----------------
#define TCK 32
__global__ __launch_bounds__(256) void k_tproj(const float* __restrict__ x) {
    int tile = blockIdx.x;
    int e = g_etile[tile];
    if (e < 0) return;
    int split = blockIdx.y, d0 = split * 256;
    int base = tile * 16;
    __shared__ float xs[16][256];         // X tile, d-contiguous per row
    __shared__ float ms[3][TCK][128];     // mixed chunks: [d][col] col<64 up, >=64 gate
    __shared__ int ps[16];
    int t = threadIdx.x;
    if (t < 16) ps[t] = g_perm[base + t];
    __syncthreads();

    // X tile via cp.async (one group): 16 rows x 64 f4
    #pragma unroll
    for (int i = 0; i < 4; i++) {
        int q = t + i * 256;
        int row = q >> 6, c4 = q & 63;
        int s = ps[row];
        unsigned sa = (unsigned)__cvta_generic_to_shared(&xs[row][c4 * 4]);
        const float* src = &x[(size_t)(s < 0 ? 0 : s) * D + d0 + c4 * 4];
        int sz = (s >= 0) ? 16 : 0;
        asm volatile("cp.async.cg.shared.global [%0], [%1], 16, %2;"
                     :: "r"(sa), "l"(src), "r"(sz));
    }
    asm volatile("cp.async.commit_group;");

    const float* upb = g_up_mixed   + (size_t)(e * D + d0) * R;
    const float* gtb = g_gate_mixed + (size_t)(e * D + d0) * R;
    auto load_ms = [&](int ck, int buf) {
        #pragma unroll
        for (int i = 0; i < 4; i++) {
            int q = t + i * 256;          // 1024 f4 slots = 32 d x 32 f4
            int d = q >> 5, c = q & 31;   // c<16: up r-slot, c>=16: gate r-slot
            const float* src = (c < 16)
                ? upb + (size_t)(ck * TCK + d) * R + c * 4
                : gtb + (size_t)(ck * TCK + d) * R + (c - 16) * 4;
            unsigned sa = (unsigned)__cvta_generic_to_shared(&ms[buf][d][c * 4]);
            asm volatile("cp.async.cg.shared.global [%0], [%1], 16, 16;"
                         :: "r"(sa), "l"(src));
        }
        asm volatile("cp.async.commit_group;");
    };

    load_ms(0, 0);
    load_ms(1, 1);

    int col = t & 127, rg = t >> 7;       // col: 0-63 up, 64-127 gate; rg: row group
    float acc[8] = {};
    const int NCK = 256 / TCK;            // 8 chunks

    for (int ck = 0; ck < NCK; ck++) {
        if (ck + 2 < NCK) { asm volatile("cp.async.wait_group 1;"); }
        else              { asm volatile("cp.async.wait_group 0;"); }
        __syncthreads();
        if (ck + 2 < NCK) load_ms(ck + 2, (ck + 2) % 3);
        const float (*mb)[128] = ms[ck % 3];
        #pragma unroll
        for (int dd = 0; dd < TCK; dd += 4) {
            float4 xv[8];
            #pragma unroll
            for (int i = 0; i < 8; i++)
                xv[i] = *(const float4*)&xs[rg * 8 + i][ck * TCK + dd];
            #pragma unroll
            for (int j = 0; j < 4; j++) {
                float m = mb[dd + j][col];
                #pragma unroll
                for (int i = 0; i < 8; i++)
                    acc[i] += ((const float*)&xv[i])[j] * m;
            }
        }
        __syncthreads();
    }
    #pragma unroll
    for (int i = 0; i < 8; i++)
        g_tpart[(size_t)(split * SPAD + base + rg * 8 + i) * 128 + col] = acc[i];
}

// ---------------- K4: expert-persistent adapters + silu -> fp16 inter ----------
// grid (22, E, 2): z splits the expert's 32-row windows for SM load balance.
// dyn smem: au[64][128] | ag[64][128] | ts[32][128] = 81920 B
__global__ __launch_bounds__(256) void k_adapt() {
    extern __shared__ float sm4[];
    float* sau = sm4;                     // [64][128]
    float* sag = sm4 + 64 * 128;          // [64][128]
    float* ts  = sm4 + 2 * 64 * 128;      // [32][128]
    int e = blockIdx.y;
    int p0 = blockIdx.x * 128;
    int t = threadIdx.x;
    int r0 = g_poff[e], r1 = g_poff[e + 1];
    int nw = (r1 - r0 + 31) >> 5;
    int hh = blockIdx.z;
    int w0 = (nw * hh) >> 1, w1 = (nw * (hh + 1)) >> 1;
    if (w0 >= w1) return;

    const float* aup = g_aut + (size_t)e * R * PP + p0;
    const float* agp = g_agt + (size_t)e * R * PP + p0;
    #pragma unroll
    for (int i = 0; i < 8; i++) {
        int q = t + i * 256;              // over 2048 f4
        int r = q >> 5, c4 = q & 31;
        unsigned sa = (unsigned)__cvta_generic_to_shared(&sau[r * 128 + c4 * 4]);
        asm volatile("cp.async.cg.shared.global [%0], [%1], 16, 16;"
                     :: "r"(sa), "l"(aup + (size_t)r * PP + c4 * 4));
        unsigned sg = (unsigned)__cvta_generic_to_shared(&sag[r * 128 + c4 * 4]);
        asm volatile("cp.async.cg.shared.global [%0], [%1], 16, 16;"
                     :: "r"(sg), "l"(agp + (size_t)r * PP + c4 * 4));
    }
    asm volatile("cp.async.commit_group;");
    asm volatile("cp.async.wait_group 0;");
    __syncthreads();

    int c = t & 31, rg = t >> 5;          // c: 4 cols each; rg: warp -> 4 rows
    for (int wI = w0; wI < w1; wI++) {
        int base = r0 + wI * 32;
        __syncthreads();                  // ts write-after-read fence
        // reduce 4 split-K partials into ts (1024 f4 / 256 thr = 4 each)
        #pragma unroll
        for (int i = 0; i < 4; i++) {
            int q = t + i * 256;
            int row = q >> 5, c4 = q & 31;
            float4 acc = make_float4(0.f, 0.f, 0.f, 0.f);
            #pragma unroll
            for (int sp = 0; sp < 4; sp++) {
                float4 v = *(const float4*)&g_tpart[(size_t)(sp * SPAD + base + row) * 128 + c4 * 4];
                acc.x += v.x; acc.y += v.y; acc.z += v.z; acc.w += v.w;
            }
            *(float4*)&ts[row * 128 + c4 * 4] = acc;
        }
        __syncthreads();

        float accu[4][4] = {}, accg[4][4] = {};
        #pragma unroll 4
        for (int r = 0; r < R; r++) {
            float4 au  = *(const float4*)&sau[r * 128 + c * 4];
            float4 ag4 = *(const float4*)&sag[r * 128 + c * 4];
            #pragma unroll
            for (int i = 0; i < 4; i++) {
                float tu  = ts[(rg * 4 + i) * 128 + r];
                float tg2 = ts[(rg * 4 + i) * 128 + 64 + r];
                accu[i][0] += tu * au.x;  accu[i][1] += tu * au.y;
                accu[i][2] += tu * au.z;  accu[i][3] += tu * au.w;
                accg[i][0] += tg2 * ag4.x; accg[i][1] += tg2 * ag4.y;
                accg[i][2] += tg2 * ag4.z; accg[i][3] += tg2 * ag4.w;
            }
        }
        #pragma unroll
        for (int i = 0; i < 4; i++) {
            int row = base + rg * 4 + i;
            if (row < r1) {
                float sv[4];
                #pragma unroll
                for (int cc = 0; cc < 4; cc++) {
                    float gv = accg[i][cc], uv = accu[i][cc];
                    sv[cc] = uv * gv / (1.f + __expf(-gv));   // up * silu(gate)
                }
                __half2 h0 = __floats2half2_rn(sv[0], sv[1]);
                __half2 h1 = __floats2half2_rn(sv[2], sv[3]);
                uint2 u;
                u.x = *(unsigned*)&h0; u.y = *(unsigned*)&h1;
                *(uint2*)&g_inter[(size_t)row * PP + p0 + c * 4] = u;
            }
        }
    }
}

// ---------------- K5: routed down GEMM, fp16 mma, K-chunk 64, coalesced fill ----
// Block 256m x 64n, 512 thr (16 warps of 32m x 32n). 3-stage ring, 64-K chunks:
// A-fill warp = 4 rows x 128B contiguous -> 4 wavefronts/warp-inst (8x fewer).
// dyn smem: A 3x36864 | Bh 3x17408 | Braw 3x16384 = 211968 B
#define KT5  64
#define NS5  (PP/KT5)       // 44
#define AS5  (256*144)      // A stage bytes: 256 rows x (128B data + 16B pad)
#define BS5  (64*272)       // B fp16 stage bytes: 64 rows x (256B + 16B pad)
#define BR5  (64*256)       // B raw fp32 stage bytes: 64 rows x 64 floats
__global__ __launch_bounds__(512) void k_down(const float* __restrict__ down,
                                              float* __restrict__ out) {
    extern __shared__ char sm5[];
    char* AshP = sm5;
    char* BshP = sm5 + 3 * AS5;
    float* Braw = (float*)(sm5 + 3 * AS5 + 3 * BS5);
    uint32_t sA = s2u(sm5);
    uint32_t sR = sA + 3 * AS5 + 3 * BS5;
    int e = blockIdx.y;
    int r0 = g_poff[e], r1 = g_poff[e + 1];
    int d0 = blockIdx.x * 64;
    const float* Bg = down + ((size_t)e * D + d0) * PP;
    int t = threadIdx.x, lane = t & 31, gq = lane >> 2, tq = lane & 3;
    int w = t >> 5, wm = w & 7, wn = w >> 3;

    for (int rowBase = r0; rowBase < r1; rowBase += 256) {
        int rem = min(256, r1 - rowBase);
        const __half* Ag = g_inter + (size_t)rowBase * PP;
        bool act = (wm * 32 < rem);       // warp has at least one real row

        auto issue = [&](int fs) {
            int buf = fs % 3;
            int kk = fs * KT5;
            #pragma unroll
            for (int i = 0; i < 4; i++) {  // A: 2048 16B chunks, 4 rows/warp coalesced
                int idx = t + i * 512;
                int row = idx >> 3, c = idx & 7;
                bool ok = row < rem;
                const __half* src = ok ? (Ag + (size_t)row * PP + kk + c * 8) : Ag;
                uint32_t sa = sA + buf * AS5 + row * 144 + c * 16;
                int sz = ok ? 16 : 0;
                asm volatile("cp.async.cg.shared.global [%0], [%1], 16, %2;"
                             :: "r"(sa), "l"(src), "r"(sz));
            }
            #pragma unroll
            for (int i = 0; i < 2; i++) {  // B raw: 1024 16B chunks, 2 rows/warp
                int idx = t + i * 512;
                int row = idx >> 4, c = idx & 15;
                const float* src = Bg + (size_t)row * PP + kk + c * 4;
                uint32_t sa = sR + buf * BR5 + row * 256 + c * 16;
                asm volatile("cp.async.cg.shared.global [%0], [%1], 16, 16;"
                             :: "r"(sa), "l"(src));
            }
            asm volatile("cp.async.commit_group;" ::: "memory");
        };
        auto convertB = [&](int cs) {      // fp32 -> fp16, 4096 floats per stage
            int buf = cs % 3;
            #pragma unroll
            for (int i = 0; i < 2; i++) {
                int idx = t + i * 512;
                int n = idx >> 4, jf = idx & 15;
                float4 v = *(const float4*)&Braw[buf * (BR5 / 4) + n * 64 + jf * 4];
                __half2 h0 = __floats2half2_rn(v.x, v.y);
                __half2 h1 = __floats2half2_rn(v.z, v.w);
                uint2 u; u.x = *(unsigned*)&h0; u.y = *(unsigned*)&h1;
                *(uint2*)(BshP + buf * BS5 + n * 272 + jf * 8) = u;
            }
        };

        issue(0); issue(1);

        float acc[2][4][4] = {};
        for (int s = 0; s < NS5; s++) {
            if (s + 1 < NS5) { asm volatile("cp.async.wait_group 1;" ::: "memory"); }
            else             { asm volatile("cp.async.wait_group 0;" ::: "memory"); }
            __syncthreads();
            if (s + 2 < NS5) issue(s + 2);
            convertB(s);
            __syncthreads();
            if (act) {
                const char* Ab = AshP + (s % 3) * AS5;
                const char* Bb = BshP + (s % 3) * BS5;
                #pragma unroll
                for (int k4 = 0; k4 < 4; k4++) {
                    int kb = k4 * 32;      // byte offset of this k16 chunk
                    unsigned a[2][4], b[4][2];
                    #pragma unroll
                    for (int mf = 0; mf < 2; mf++) {
                        int mr = wm * 32 + mf * 16 + gq;
                        a[mf][0] = *(const unsigned*)(Ab +  mr      * 144 + kb + tq * 4);
                        a[mf][1] = *(const unsigned*)(Ab + (mr + 8) * 144 + kb + tq * 4);
                        a[mf][2] = *(const unsigned*)(Ab +  mr      * 144 + kb + 16 + tq * 4);
                        a[mf][3] = *(const unsigned*)(Ab + (mr + 8) * 144 + kb + 16 + tq * 4);
                    }
                    #pragma unroll
                    for (int nf = 0; nf < 4; nf++) {
                        int nr = wn * 32 + nf * 8 + gq;
                        b[nf][0] = *(const unsigned*)(Bb + nr * 272 + kb + tq * 4);
                        b[nf][1] = *(const unsigned*)(Bb + nr * 272 + kb + 16 + tq * 4);
                    }
                    #pragma unroll
                    for (int mf = 0; mf < 2; mf++)
                        #pragma unroll
                        for (int nf = 0; nf < 4; nf++)
                            asm volatile(
                                "mma.sync.aligned.m16n8k16.row.col.f32.f16.f16.f32 "
                                "{%0,%1,%2,%3}, {%4,%5,%6,%7}, {%8,%9}, {%0,%1,%2,%3};"
                                : "+f"(acc[mf][nf][0]), "+f"(acc[mf][nf][1]),
                                  "+f"(acc[mf][nf][2]), "+f"(acc[mf][nf][3])
                                : "r"(a[mf][0]), "r"(a[mf][1]), "r"(a[mf][2]), "r"(a[mf][3]),
                                  "r"(b[nf][0]), "r"(b[nf][1]));
                }
            }
        }
        // epilogue: scale by routing weight, scatter to original token rows
        if (act) {
            #pragma unroll
            for (int mf = 0; mf < 2; mf++) {
                #pragma unroll
                for (int h = 0; h < 2; h++) {
                    int m = wm * 32 + mf * 16 + gq + h * 8;
                    if (m < rem) {
                        int s = g_perm[rowBase + m];
                        if (s >= 0) {
                            float wv = g_wrow[rowBase + m];
                            #pragma unroll
                            for (int nf = 0; nf < 4; nf++) {
                                int n = d0 + wn * 32 + nf * 8 + tq * 2;
                                float2 v;
                                v.x = acc[mf][nf][h * 2 + 0] * wv;
                                v.y = acc[mf][nf][h * 2 + 1] * wv;
                                *(float2*)&out[(size_t)s * D + n] = v;
                            }
                        }
                    }
                }
            }
        }
        __syncthreads();                  // reuse smem next rowBase iter
    }
}

// ---------------- launch ----------------
extern "C" void kernel_launch(void* const* d_in, const int* in_sizes, int n_in,
                              void* d_out, int out_size) {
    const float* x     = (const float*)d_in[0];
    const int*   eidx  = (const int*)  d_in[1];
    const float* ew    = (const float*)d_in[2];
    const float* uA    = (const float*)d_in[3];
    const float* gA    = (const float*)d_in[4];
    const float* ulog  = (const float*)d_in[5];
    const float* glog  = (const float*)d_in[6];
    const float* down  = (const float*)d_in[7];
    const float* ubank = (const float*)d_in[8];
    const float* gbank = (const float*)d_in[9];
    float* out = (float*)d_out;

    const int ADAPT_SMEM = (2 * 64 * 128 + 32 * 128) * 4;   // 81920
    const int DOWN_SMEM  = 3 * AS5 + 3 * BS5 + 3 * BR5;      // 211968
    cudaFuncSetAttribute(k_adapt, cudaFuncAttributeMaxDynamicSharedMemorySize, ADAPT_SMEM);
    cudaFuncSetAttribute(k_down,  cudaFuncAttributeMaxDynamicSharedMemorySize, DOWN_SMEM);

    k_route<<<1, 1024>>>(eidx, ew, ulog, glog);
    k_mixed<<<256, 256>>>(ubank, gbank);
    k_trans<<<dim3(PP / 32, R / 32, 2 * E), dim3(32, 8)>>>(uA, gA);
    k_tproj<<<dim3(NT, 4), 256>>>(x);
    k_adapt<<<dim3(PP / 128, E, 2), 256, ADAPT_SMEM>>>();
    k_down<<<dim3(D / 64, E), 512, DOWN_SMEM>>>(down, out);
}

// round 17
// speedup vs baseline: 1.5195x; 1.2181x over previous
#include <cuda_runtime.h>
#include <cuda_fp16.h>
#include <cstdint>

#define S    1024
#define D    1024
#define PP   2816
#define R    64
#define E    8
#define MM   16
#define SPAD 1152
#define NT   (SPAD/16)   // 72 sixteen-row tiles

// ---------------- device scratch (static, no runtime alloc) ----------------
__device__ float g_alpha[2][E][MM];          // softmax mixture weights (0=up,1=gate)
__device__ float g_up_mixed[E*D*R];          // [E][D][R]
__device__ float g_gate_mixed[E*D*R];
__device__ __half g_auh[E*PP*R];             // fp16 up adapters [E][P][R] (orig layout)
__device__ __half g_agh[E*PP*R];             // fp16 gate adapters
__device__ int   g_perm[SPAD];               // permuted row -> token (or -1 pad)
__device__ float g_wrow[SPAD];               // routing weight per permuted row
__device__ int   g_poff[E+1];                // padded expert offsets (mult of 16)
__device__ int   g_etile[NT];                // expert per 16-row tile (or -1)
__device__ float g_tpart[4*SPAD*2*R + 64*128]; // split-K partials (+pad)
__device__ __half g_tsum[(SPAD+32)*128];     // reduced t (up|gate) fp16 (+pad rows)
__device__ __half g_inter[SPAD*PP];          // silu(gate)*up, fp16

__device__ __forceinline__ uint32_t s2u(const void* p) {
    uint32_t a;
    asm("{ .reg .u64 t; cvta.to.shared.u64 t, %1; cvt.u32.u64 %0, t; }" : "=r"(a) : "l"(p));
    return a;
}

// ---------------- K1: routing, permutation, alphas ----------------
__global__ __launch_bounds__(1024) void k_route(const int* __restrict__ eidx,
                                                const float* __restrict__ ew,
                                                const float* __restrict__ ulog,
                                                const float* __restrict__ glog) {
    __shared__ int wcnt[32][E];
    __shared__ int woff[32][E];
    __shared__ int poff_s[E+1];
    int t = threadIdx.x;
    int e = eidx[t];                      // K = 1
    int w = t >> 5, lane = t & 31;
    if (lane < E) wcnt[w][lane] = 0;
    __syncthreads();
    unsigned mask = __match_any_sync(0xffffffffu, e);
    int posw = __popc(mask & ((1u << lane) - 1u));
    if (posw == 0) wcnt[w][e] = __popc(mask);
    __syncthreads();
    if (t < 256) {                        // exclusive prefix over warps per expert
        int e2 = t >> 5, w2 = t & 31;
        int sacc = 0;
        for (int ww = 0; ww < w2; ww++) sacc += wcnt[ww][e2];
        woff[w2][e2] = sacc;
    }
    __syncthreads();
    if (t == 0) {
        int o = 0;
        for (int e2 = 0; e2 < E; e2++) {
            poff_s[e2] = o;
            int c = woff[31][e2] + wcnt[31][e2];
            o += (c + 15) & ~15;          // pad each expert to 16 rows
        }
        poff_s[E] = o;
        for (int i = 0; i <= E; i++) g_poff[i] = poff_s[i];
    }
    __syncthreads();
    for (int i = t; i < SPAD; i += 1024) { g_perm[i] = -1; g_wrow[i] = 0.f; }
    __syncthreads();
    int row = poff_s[e] + woff[w][e] + posw;
    g_perm[row] = t;
    g_wrow[row] = ew[t];
    if (t < NT) {
        int r0 = t * 16; int ee = -1;
        for (int e2 = 0; e2 < E; e2++)
            if (r0 >= poff_s[e2] && r0 < poff_s[e2+1]) ee = e2;
        g_etile[t] = ee;
    }
    if (t < 2 * E) {                      // softmax over M=16
        int which = t & 1, e2 = t >> 1;
        const float* L = (which ? glog : ulog) + e2 * MM;
        float mx = L[0];
        for (int m = 1; m < MM; m++) mx = fmaxf(mx, L[m]);
        float sum = 0.f, ex[MM];
        for (int m = 0; m < MM; m++) { ex[m] = __expf(L[m] - mx); sum += ex[m]; }
        float inv = 1.f / sum;
        for (int m = 0; m < MM; m++) g_alpha[which][e2][m] = ex[m] * inv;
    }
}

// ---------------- K2: mixed bases [E,D,R] = alpha @ bank ----------------
__global__ __launch_bounds__(256) void k_mixed(const float* __restrict__ ubank,
                                               const float* __restrict__ gbank) {
    __shared__ float al[2 * E * MM];      // 256 floats
    int t = threadIdx.x;
    al[t] = ((const float*)g_alpha)[t];
    __syncthreads();
    int r = t & 63, dl = t >> 6;
    int d = blockIdx.x * 4 + dl;
    float au[E], ag[E];
    #pragma unroll
    for (int e = 0; e < E; e++) { au[e] = 0.f; ag[e] = 0.f; }
    #pragma unroll
    for (int m = 0; m < MM; m++) {
        float bu = ubank[(m * D + d) * R + r];
        float bg = gbank[(m * D + d) * R + r];
        #pragma unroll
        for (int e = 0; e < E; e++) {
            au[e] += al[e * MM + m] * bu;
            ag[e] += al[E * MM + e * MM + m] * bg;
        }
    }
    #pragma unroll
    for (int e = 0; e < E; e++) {
        g_up_mixed  [(e * D + d) * R + r] = au[e];
        g_gate_mixed[(e * D + d) * R + r] = ag[e];
    }
}

// ---------------- K2b: convert adapters fp32 -> fp16 (original [E][P][R] layout) --
__global__ __launch_bounds__(256) void k_cvtA(const float* __restrict__ uA,
                                              const float* __restrict__ gA) {
    int which = blockIdx.y;
    const float* src = which ? gA : uA;
    __half* dst = which ? g_agh : g_auh;
    size_t i4 = (size_t)blockIdx.x * 256 + threadIdx.x;
    const size_t n4 = (size_t)E * PP * R / 4;
    if (i4 < n4) {
        float4 v = *(const float4*)(src + i4 * 4);
        __half2 h0 = __floats2half2_rn(v.x, v.y);
        __half2 h1 = __floats2half2_rn(v.z, v.w);
        uint2 u; u.x = *(unsigned*)&h0; u.y = *(unsigned*)&h1;
        *(uint2*)(dst + i4 * 4) = u;
    }
}

// ---------------- K3: t = X_gathered @ mixed (split-K=4, pipelined smem) ----------------
#define TCK 32
__global__ __launch_bounds__(256) void k_tproj(const float* __restrict__ x) {
    int tile = blockIdx.x;
    int e = g_etile[tile];
    if (e < 0) return;
    int split = blockIdx.y, d0 = split * 256;
    int base = tile * 16;
    __shared__ float xs[16][256];         // X tile, d-contiguous per row
    __shared__ float ms[3][TCK][128];     // mixed chunks: [d][col] col<64 up, >=64 gate
    __shared__ int ps[16];
    int t = threadIdx.x;
    if (t < 16) ps[t] = g_perm[base + t];
    __syncthreads();

    // X tile via cp.async (one group): 16 rows x 64 f4
    #pragma unroll
    for (int i = 0; i < 4; i++) {
        int q = t + i * 256;
        int row = q >> 6, c4 = q & 63;
        int s = ps[row];
        unsigned sa = (unsigned)__cvta_generic_to_shared(&xs[row][c4 * 4]);
        const float* src = &x[(size_t)(s < 0 ? 0 : s) * D + d0 + c4 * 4];
        int sz = (s >= 0) ? 16 : 0;
        asm volatile("cp.async.cg.shared.global [%0], [%1], 16, %2;"
                     :: "r"(sa), "l"(src), "r"(sz));
    }
    asm volatile("cp.async.commit_group;");

    const float* upb = g_up_mixed   + (size_t)(e * D + d0) * R;
    const float* gtb = g_gate_mixed + (size_t)(e * D + d0) * R;
    auto load_ms = [&](int ck, int buf) {
        #pragma unroll
        for (int i = 0; i < 4; i++) {
            int q = t + i * 256;          // 1024 f4 slots = 32 d x 32 f4
            int d = q >> 5, c = q & 31;   // c<16: up r-slot, c>=16: gate r-slot
            const float* src = (c < 16)
                ? upb + (size_t)(ck * TCK + d) * R + c * 4
                : gtb + (size_t)(ck * TCK + d) * R + (c - 16) * 4;
            unsigned sa = (unsigned)__cvta_generic_to_shared(&ms[buf][d][c * 4]);
            asm volatile("cp.async.cg.shared.global [%0], [%1], 16, 16;"
                         :: "r"(sa), "l"(src));
        }
        asm volatile("cp.async.commit_group;");
    };

    load_ms(0, 0);
    load_ms(1, 1);

    int col = t & 127, rg = t >> 7;       // col: 0-63 up, 64-127 gate; rg: row group
    float acc[8] = {};
    const int NCK = 256 / TCK;            // 8 chunks

    for (int ck = 0; ck < NCK; ck++) {
        if (ck + 2 < NCK) { asm volatile("cp.async.wait_group 1;"); }
        else              { asm volatile("cp.async.wait_group 0;"); }
        __syncthreads();
        if (ck + 2 < NCK) load_ms(ck + 2, (ck + 2) % 3);
        const float (*mb)[128] = ms[ck % 3];
        #pragma unroll
        for (int dd = 0; dd < TCK; dd += 4) {
            float4 xv[8];
            #pragma unroll
            for (int i = 0; i < 8; i++)
                xv[i] = *(const float4*)&xs[rg * 8 + i][ck * TCK + dd];
            #pragma unroll
            for (int j = 0; j < 4; j++) {
                float m = mb[dd + j][col];
                #pragma unroll
                for (int i = 0; i < 8; i++)
                    acc[i] += ((const float*)&xv[i])[j] * m;
            }
        }
        __syncthreads();
    }
    #pragma unroll
    for (int i = 0; i < 8; i++)
        g_tpart[(size_t)(split * SPAD + base + rg * 8 + i) * 128 + col] = acc[i];
}

// ---------------- K3b: reduce split-K partials once, convert to fp16 ------------
__global__ __launch_bounds__(256) void k_tsum() {
    int base = blockIdx.x * 32;
    int t = threadIdx.x;
    #pragma unroll
    for (int i = 0; i < 4; i++) {
        int q = t + i * 256;              // 1024 slots = 32 rows x 32 c4-groups
        int row = q >> 5, c4 = q & 31;
        float4 acc = make_float4(0.f, 0.f, 0.f, 0.f);
        #pragma unroll
        for (int sp = 0; sp < 4; sp++) {
            float4 v = *(const float4*)&g_tpart[(size_t)(sp * SPAD + base + row) * 128 + c4 * 4];
            acc.x += v.x; acc.y += v.y; acc.z += v.z; acc.w += v.w;
        }
        __half2 h0 = __floats2half2_rn(acc.x, acc.y);
        __half2 h1 = __floats2half2_rn(acc.z, acc.w);
        uint2 u; u.x = *(unsigned*)&h0; u.y = *(unsigned*)&h1;
        *(uint2*)&g_tsum[(size_t)(base + row) * 128 + c4 * 4] = u;
    }
}

// ---------------- K4: adapters + silu via fp16 mma ------------------------------
// grid (22, E, 2). Block: 128 p-cols, 32-row windows. 8 warps = 2m x 4n.
// smem: bu[128][144B] | bg[128][144B] | ts[32][272B] = 45568 B
#define AUP 144
#define TSP 272
__global__ __launch_bounds__(256) void k_adapt() {
    extern __shared__ char sm4[];
    uint32_t sbu = s2u(sm4);
    uint32_t sbg = sbu + 128 * AUP;
    uint32_t sts = sbu + 2 * 128 * AUP;
    char* buP = sm4;
    char* bgP = sm4 + 128 * AUP;
    char* tsP = sm4 + 2 * 128 * AUP;
    int e = blockIdx.y, p0 = blockIdx.x * 128, t = threadIdx.x;
    int r0 = g_poff[e], r1 = g_poff[e + 1];
    int nw = (r1 - r0 + 31) >> 5;
    int hh = blockIdx.z;
    int w0 = (nw * hh) >> 1, w1 = (nw * (hh + 1)) >> 1;
    if (w0 >= w1) return;

    // stage fp16 adapters once: 128 p-rows x 64 r halfs (128B) each
    const __half* Au = g_auh + ((size_t)e * PP + p0) * R;
    const __half* Ag = g_agh + ((size_t)e * PP + p0) * R;
    #pragma unroll
    for (int i = 0; i < 4; i++) {
        int idx = t + i * 256, row = idx >> 3, c = idx & 7;
        asm volatile("cp.async.cg.shared.global [%0], [%1], 16, 16;"
                     :: "r"(sbu + row * AUP + c * 16), "l"(Au + (size_t)row * R + c * 8));
        asm volatile("cp.async.cg.shared.global [%0], [%1], 16, 16;"
                     :: "r"(sbg + row * AUP + c * 16), "l"(Ag + (size_t)row * R + c * 8));
    }
    asm volatile("cp.async.commit_group;");
    asm volatile("cp.async.wait_group 0;");

    int lane = t & 31, gq = lane >> 2, tq = lane & 3;
    int w = t >> 5, wm = w & 1, wn = w >> 1;

    for (int wI = w0; wI < w1; wI++) {
        int base = r0 + wI * 32;
        __syncthreads();                  // prior window's readers done
        #pragma unroll
        for (int i = 0; i < 2; i++) {     // ts tile: 32 rows x 256B
            int idx = t + i * 256, row = idx >> 4, c = idx & 15;
            asm volatile("cp.async.cg.shared.global [%0], [%1], 16, 16;"
                         :: "r"(sts + row * TSP + c * 16),
                            "l"(g_tsum + (size_t)(base + row) * 128 + c * 8));
        }
        asm volatile("cp.async.commit_group;");
        asm volatile("cp.async.wait_group 0;");
        __syncthreads();

        float au4[4][4] = {}, ag4[4][4] = {};
        #pragma unroll
        for (int ks = 0; ks < 4; ks++) {
            int kb = ks * 32;
            const char* Ar = tsP + (wm * 16 + gq) * TSP;
            unsigned aU[4], aG[4];
            aU[0] = *(const unsigned*)(Ar + kb + tq * 4);
            aU[1] = *(const unsigned*)(Ar + 8 * TSP + kb + tq * 4);
            aU[2] = *(const unsigned*)(Ar + kb + 16 + tq * 4);
            aU[3] = *(const unsigned*)(Ar + 8 * TSP + kb + 16 + tq * 4);
            aG[0] = *(const unsigned*)(Ar + 128 + kb + tq * 4);
            aG[1] = *(const unsigned*)(Ar + 8 * TSP + 128 + kb + tq * 4);
            aG[2] = *(const unsigned*)(Ar + 128 + kb + 16 + tq * 4);
            aG[3] = *(const unsigned*)(Ar + 8 * TSP + 128 + kb + 16 + tq * 4);
            #pragma unroll
            for (int nf = 0; nf < 4; nf++) {
                int nr = wn * 32 + nf * 8 + gq;
                unsigned b0u = *(const unsigned*)(buP + nr * AUP + kb + tq * 4);
                unsigned b1u = *(const unsigned*)(buP + nr * AUP + kb + 16 + tq * 4);
                asm volatile(
                    "mma.sync.aligned.m16n8k16.row.col.f32.f16.f16.f32 "
                    "{%0,%1,%2,%3}, {%4,%5,%6,%7}, {%8,%9}, {%0,%1,%2,%3};"
                    : "+f"(au4[nf][0]), "+f"(au4[nf][1]), "+f"(au4[nf][2]), "+f"(au4[nf][3])
                    : "r"(aU[0]), "r"(aU[1]), "r"(aU[2]), "r"(aU[3]), "r"(b0u), "r"(b1u));
                unsigned b0g = *(const unsigned*)(bgP + nr * AUP + kb + tq * 4);
                unsigned b1g = *(const unsigned*)(bgP + nr * AUP + kb + 16 + tq * 4);
                asm volatile(
                    "mma.sync.aligned.m16n8k16.row.col.f32.f16.f16.f32 "
                    "{%0,%1,%2,%3}, {%4,%5,%6,%7}, {%8,%9}, {%0,%1,%2,%3};"
                    : "+f"(ag4[nf][0]), "+f"(ag4[nf][1]), "+f"(ag4[nf][2]), "+f"(ag4[nf][3])
                    : "r"(aG[0]), "r"(aG[1]), "r"(aG[2]), "r"(aG[3]), "r"(b0g), "r"(b1g));
            }
        }
        // epilogue: silu combine in C fragments, store half2
        #pragma unroll
        for (int nf = 0; nf < 4; nf++) {
            #pragma unroll
            for (int h = 0; h < 2; h++) {
                int row = base + wm * 16 + gq + h * 8;
                if (row < r1) {
                    float uv0 = au4[nf][h * 2 + 0], uv1 = au4[nf][h * 2 + 1];
                    float gv0 = ag4[nf][h * 2 + 0], gv1 = ag4[nf][h * 2 + 1];
                    float s0 = uv0 * gv0 / (1.f + __expf(-gv0));
                    float s1 = uv1 * gv1 / (1.f + __expf(-gv1));
                    __half2 h2 = __floats2half2_rn(s0, s1);
                    *(unsigned*)&g_inter[(size_t)row * PP + p0 + wn * 32 + nf * 8 + tq * 2]
                        = *(unsigned*)&h2;
                }
            }
        }
    }
}

// ---------------- K5: routed down GEMM, fp16 mma, K-chunk 64, coalesced fill ----
#define KT5  64
#define NS5  (PP/KT5)       // 44
#define AS5  (256*144)      // A stage bytes: 256 rows x (128B data + 16B pad)
#define BS5  (64*272)       // B fp16 stage bytes: 64 rows x (256B + 16B pad)
#define BR5  (64*256)       // B raw fp32 stage bytes: 64 rows x 64 floats
__global__ __launch_bounds__(512) void k_down(const float* __restrict__ down,
                                              float* __restrict__ out) {
    extern __shared__ char sm5[];
    char* AshP = sm5;
    char* BshP = sm5 + 3 * AS5;
    float* Braw = (float*)(sm5 + 3 * AS5 + 3 * BS5);
    uint32_t sA = s2u(sm5);
    uint32_t sR = sA + 3 * AS5 + 3 * BS5;
    int e = blockIdx.y;
    int r0 = g_poff[e], r1 = g_poff[e + 1];
    int d0 = blockIdx.x * 64;
    const float* Bg = down + ((size_t)e * D + d0) * PP;
    int t = threadIdx.x, lane = t & 31, gq = lane >> 2, tq = lane & 3;
    int w = t >> 5, wm = w & 7, wn = w >> 3;

    for (int rowBase = r0; rowBase < r1; rowBase += 256) {
        int rem = min(256, r1 - rowBase);
        const __half* Ag = g_inter + (size_t)rowBase * PP;
        bool act = (wm * 32 < rem);       // warp has at least one real row

        auto issue = [&](int fs) {
            int buf = fs % 3;
            int kk = fs * KT5;
            #pragma unroll
            for (int i = 0; i < 4; i++) {  // A: 2048 16B chunks, 4 rows/warp coalesced
                int idx = t + i * 512;
                int row = idx >> 3, c = idx & 7;
                bool ok = row < rem;
                const __half* src = ok ? (Ag + (size_t)row * PP + kk + c * 8) : Ag;
                uint32_t sa = sA + buf * AS5 + row * 144 + c * 16;
                int sz = ok ? 16 : 0;
                asm volatile("cp.async.cg.shared.global [%0], [%1], 16, %2;"
                             :: "r"(sa), "l"(src), "r"(sz));
            }
            #pragma unroll
            for (int i = 0; i < 2; i++) {  // B raw: 1024 16B chunks, 2 rows/warp
                int idx = t + i * 512;
                int row = idx >> 4, c = idx & 15;
                const float* src = Bg + (size_t)row * PP + kk + c * 4;
                uint32_t sa = sR + buf * BR5 + row * 256 + c * 16;
                asm volatile("cp.async.cg.shared.global [%0], [%1], 16, 16;"
                             :: "r"(sa), "l"(src));
            }
            asm volatile("cp.async.commit_group;" ::: "memory");
        };
        auto convertB = [&](int cs) {      // fp32 -> fp16, 4096 floats per stage
            int buf = cs % 3;
            #pragma unroll
            for (int i = 0; i < 2; i++) {
                int idx = t + i * 512;
                int n = idx >> 4, jf = idx & 15;
                float4 v = *(const float4*)&Braw[buf * (BR5 / 4) + n * 64 + jf * 4];
                __half2 h0 = __floats2half2_rn(v.x, v.y);
                __half2 h1 = __floats2half2_rn(v.z, v.w);
                uint2 u; u.x = *(unsigned*)&h0; u.y = *(unsigned*)&h1;
                *(uint2*)(BshP + buf * BS5 + n * 272 + jf * 8) = u;
            }
        };

        issue(0); issue(1);

        float acc[2][4][4] = {};
        for (int s = 0; s < NS5; s++) {
            if (s + 1 < NS5) { asm volatile("cp.async.wait_group 1;" ::: "memory"); }
            else             { asm volatile("cp.async.wait_group 0;" ::: "memory"); }
            __syncthreads();
            if (s + 2 < NS5) issue(s + 2);
            convertB(s);
            __syncthreads();
            if (act) {
                const char* Ab = AshP + (s % 3) * AS5;
                const char* Bb = BshP + (s % 3) * BS5;
                #pragma unroll
                for (int k4 = 0; k4 < 4; k4++) {
                    int kb = k4 * 32;      // byte offset of this k16 chunk
                    unsigned a[2][4], b[4][2];
                    #pragma unroll
                    for (int mf = 0; mf < 2; mf++) {
                        int mr = wm * 32 + mf * 16 + gq;
                        a[mf][0] = *(const unsigned*)(Ab +  mr      * 144 + kb + tq * 4);
                        a[mf][1] = *(const unsigned*)(Ab + (mr + 8) * 144 + kb + tq * 4);
                        a[mf][2] = *(const unsigned*)(Ab +  mr      * 144 + kb + 16 + tq * 4);
                        a[mf][3] = *(const unsigned*)(Ab + (mr + 8) * 144 + kb + 16 + tq * 4);
                    }
                    #pragma unroll
                    for (int nf = 0; nf < 4; nf++) {
                        int nr = wn * 32 + nf * 8 + gq;
                        b[nf][0] = *(const unsigned*)(Bb + nr * 272 + kb + tq * 4);
                        b[nf][1] = *(const unsigned*)(Bb + nr * 272 + kb + 16 + tq * 4);
                    }
                    #pragma unroll
                    for (int mf = 0; mf < 2; mf++)
                        #pragma unroll
                        for (int nf = 0; nf < 4; nf++)
                            asm volatile(
                                "mma.sync.aligned.m16n8k16.row.col.f32.f16.f16.f32 "
                                "{%0,%1,%2,%3}, {%4,%5,%6,%7}, {%8,%9}, {%0,%1,%2,%3};"
                                : "+f"(acc[mf][nf][0]), "+f"(acc[mf][nf][1]),
                                  "+f"(acc[mf][nf][2]), "+f"(acc[mf][nf][3])
                                : "r"(a[mf][0]), "r"(a[mf][1]), "r"(a[mf][2]), "r"(a[mf][3]),
                                  "r"(b[nf][0]), "r"(b[nf][1]));
                }
            }
        }
        // epilogue: scale by routing weight, scatter to original token rows
        if (act) {
            #pragma unroll
            for (int mf = 0; mf < 2; mf++) {
                #pragma unroll
                for (int h = 0; h < 2; h++) {
                    int m = wm * 32 + mf * 16 + gq + h * 8;
                    if (m < rem) {
                        int s = g_perm[rowBase + m];
                        if (s >= 0) {
                            float wv = g_wrow[rowBase + m];
                            #pragma unroll
                            for (int nf = 0; nf < 4; nf++) {
                                int n = d0 + wn * 32 + nf * 8 + tq * 2;
                                float2 v;
                                v.x = acc[mf][nf][h * 2 + 0] * wv;
                                v.y = acc[mf][nf][h * 2 + 1] * wv;
                                *(float2*)&out[(size_t)s * D + n] = v;
                            }
                        }
                    }
                }
            }
        }
        __syncthreads();                  // reuse smem next rowBase iter
    }
}

// ---------------- launch ----------------
extern "C" void kernel_launch(void* const* d_in, const int* in_sizes, int n_in,
                              void* d_out, int out_size) {
    const float* x     = (const float*)d_in[0];
    const int*   eidx  = (const int*)  d_in[1];
    const float* ew    = (const float*)d_in[2];
    const float* uA    = (const float*)d_in[3];
    const float* gA    = (const float*)d_in[4];
    const float* ulog  = (const float*)d_in[5];
    const float* glog  = (const float*)d_in[6];
    const float* down  = (const float*)d_in[7];
    const float* ubank = (const float*)d_in[8];
    const float* gbank = (const float*)d_in[9];
    float* out = (float*)d_out;

    const int ADAPT_SMEM = 2 * 128 * AUP + 32 * TSP;         // 45568
    const int DOWN_SMEM  = 3 * AS5 + 3 * BS5 + 3 * BR5;      // 211968
    cudaFuncSetAttribute(k_adapt, cudaFuncAttributeMaxDynamicSharedMemorySize, ADAPT_SMEM);
    cudaFuncSetAttribute(k_down,  cudaFuncAttributeMaxDynamicSharedMemorySize, DOWN_SMEM);

    const int CVT_BLOCKS = (int)(((size_t)E * PP * R / 4 + 255) / 256);   // 1408

    k_route<<<1, 1024>>>(eidx, ew, ulog, glog);
    k_mixed<<<256, 256>>>(ubank, gbank);
    k_cvtA<<<dim3(CVT_BLOCKS, 2), 256>>>(uA, gA);
    k_tproj<<<dim3(NT, 4), 256>>>(x);
    k_tsum<<<(SPAD + 32) / 32, 256>>>();
    k_adapt<<<dim3(PP / 128, E, 2), 256, ADAPT_SMEM>>>();
    k_down<<<dim3(D / 64, E), 512, DOWN_SMEM>>>(down, out);
}